// round 2
// baseline (speedup 1.0000x reference)
#include <cuda_runtime.h>
#include <cuda_fp16.h>
#include <stdint.h>

#define B_  16384
#define D_  4096
#define K_  14
#define QP  16          // padded K for q matrices (float4-friendly)

#define BM 128
#define BN 128
#define BK 32
#define KSTRIDE (BK + 8)   // padded smem row stride in halves (80B, 16B-aligned)
#define KTILES (D_ / BK)

// ---------------- scratch (device globals; no allocations allowed) --------
__device__ float g_phat [K_ * D_];
__device__ float g_qv   [D_ * QP];
__device__ float g_qt   [D_ * QP];
__device__ float g_cv   [K_];
__device__ float g_ct   [K_];
__device__ float g_normv[B_];
__device__ float g_normt[B_];
__device__ int   g_bcc  [K_ * K_];

// ---------------- helpers --------------------------------------------------
__device__ __forceinline__ uint32_t smem_u32(const void* p) {
    return (uint32_t)__cvta_generic_to_shared(p);
}

__device__ __forceinline__ void ldsm_x4(uint32_t* r, uint32_t addr) {
    asm volatile("ldmatrix.sync.aligned.m8n8.x4.shared.b16 {%0,%1,%2,%3}, [%4];"
                 : "=r"(r[0]), "=r"(r[1]), "=r"(r[2]), "=r"(r[3]) : "r"(addr));
}
__device__ __forceinline__ void ldsm_x2(uint32_t* r, uint32_t addr) {
    asm volatile("ldmatrix.sync.aligned.m8n8.x2.shared.b16 {%0,%1}, [%2];"
                 : "=r"(r[0]), "=r"(r[1]) : "r"(addr));
}
__device__ __forceinline__ void mma16816(float* c, const uint32_t* a, const uint32_t* b) {
    asm volatile(
        "mma.sync.aligned.m16n8k16.row.col.f32.f16.f16.f32 "
        "{%0,%1,%2,%3}, {%4,%5,%6,%7}, {%8,%9}, {%0,%1,%2,%3};"
        : "+f"(c[0]), "+f"(c[1]), "+f"(c[2]), "+f"(c[3])
        : "r"(a[0]), "r"(a[1]), "r"(a[2]), "r"(a[3]), "r"(b[0]), "r"(b[1]));
}
__device__ __forceinline__ uint2 f4_to_h4(float4 v) {
    __half2 a = __floats2half2_rn(v.x, v.y);
    __half2 b = __floats2half2_rn(v.z, v.w);
    uint2 r;
    r.x = *reinterpret_cast<uint32_t*>(&a);
    r.y = *reinterpret_cast<uint32_t*>(&b);
    return r;
}

// ---------------- zero scratch ---------------------------------------------
__global__ void zero_kernel() {
    int idx = blockIdx.x * blockDim.x + threadIdx.x;   // 65536 threads
    if (idx < D_ * QP) { g_qv[idx] = 0.f; g_qt[idx] = 0.f; }
    if (idx < B_)      { g_normv[idx] = 0.f; g_normt[idx] = 0.f; }
    if (idx < K_ * K_) g_bcc[idx] = 0;
}

// ---------------- normalize prototypes + bias dots ---------------------------
// block k: p_hat[k] = p[k]/max(||p[k]||,eps);  cv[k]=bv.p_hat[k]; ct[k]=bt.p_hat[k]
__global__ void phat_kernel(const float* __restrict__ proto,
                            const float* __restrict__ bv,
                            const float* __restrict__ bt) {
    int k = blockIdx.x, tid = threadIdx.x;
    float ss = 0.f, sv = 0.f, st = 0.f;
    for (int i = tid; i < D_; i += 256) {
        float p = proto[k * D_ + i];
        ss += p * p; sv += p * bv[i]; st += p * bt[i];
    }
    for (int off = 16; off; off >>= 1) {
        ss += __shfl_xor_sync(~0u, ss, off);
        sv += __shfl_xor_sync(~0u, sv, off);
        st += __shfl_xor_sync(~0u, st, off);
    }
    __shared__ float r0[8], r1[8], r2[8];
    __shared__ float s_inv;
    int warp = tid >> 5, lane = tid & 31;
    if (lane == 0) { r0[warp] = ss; r1[warp] = sv; r2[warp] = st; }
    __syncthreads();
    if (tid == 0) {
        float S = 0.f, V = 0.f, T = 0.f;
        for (int w = 0; w < 8; w++) { S += r0[w]; V += r1[w]; T += r2[w]; }
        float inv = 1.0f / fmaxf(sqrtf(S), 1e-12f);
        s_inv = inv;
        g_cv[k] = V * inv;
        g_ct[k] = T * inv;
    }
    __syncthreads();
    float inv = s_inv;
    for (int i = tid; i < D_; i += 256)
        g_phat[k * D_ + i] = proto[k * D_ + i] * inv;
}

// ---------------- q = W^T @ p_hat^T  ([D, K] padded to QP) -------------------
// grid (16, 8, 2): x -> i chunk (256 i's), y -> j chunk (512 j's), z -> {Wv,Wt}
__global__ void q_kernel(const float* __restrict__ Wv, const float* __restrict__ Wt) {
    const float* W = blockIdx.z ? Wt : Wv;
    float* q = blockIdx.z ? g_qt : g_qv;
    int i  = blockIdx.x * 256 + threadIdx.x;
    int j0 = blockIdx.y * 512;
    __shared__ float ps[K_][512];
    for (int idx = threadIdx.x; idx < K_ * 512; idx += 256) {
        int k = idx >> 9, j = idx & 511;
        ps[k][j] = g_phat[k * D_ + j0 + j];
    }
    __syncthreads();
    float acc[K_];
#pragma unroll
    for (int k = 0; k < K_; k++) acc[k] = 0.f;
    for (int jj = 0; jj < 512; ++jj) {
        float w = W[(size_t)(j0 + jj) * D_ + i];
#pragma unroll
        for (int k = 0; k < K_; k++) acc[k] += w * ps[k][jj];
    }
#pragma unroll
    for (int k = 0; k < K_; k++) atomicAdd(&q[i * QP + k], acc[k]);
}

// ---------------- big GEMM: row norms of X @ W^T + bias ----------------------
// fp32 inputs converted to fp16 on the fly, fp32 accumulation via HMMA.
// grid (D_/BN, B_/BM); 256 threads = 8 warps in 2(M) x 4(N) layout.
__global__ void __launch_bounds__(256)
norm_gemm(const float* __restrict__ X, const float* __restrict__ W,
          const float* __restrict__ bias, int which) {
    float* normOut = which ? g_normt : g_normv;

    __shared__ __align__(16) half As[2][BM][KSTRIDE];
    __shared__ __align__(16) half Bs[2][BN][KSTRIDE];
    __shared__ float sb[BN];

    const int tid  = threadIdx.x;
    const int lane = tid & 31;
    const int warp = tid >> 5;
    const int wm = warp & 1;        // 0..1  (64-row slab)
    const int wn = warp >> 1;       // 0..3  (32-col slab)
    const int m0 = blockIdx.y * BM;
    const int n0 = blockIdx.x * BN;

    if (tid < BN) sb[tid] = bias[n0 + tid];

    const float4* Xv = (const float4*)X;
    const float4* Wv4 = (const float4*)W;

    float acc[4][4][4];
#pragma unroll
    for (int mi = 0; mi < 4; mi++)
#pragma unroll
        for (int ni = 0; ni < 4; ni++)
#pragma unroll
            for (int c = 0; c < 4; c++) acc[mi][ni][c] = 0.f;

    float4 ra[4], rb[4];

#define LDG_STAGE(kt)                                                     \
    {                                                                     \
        int kb = (kt) * 8;                                                \
        for (int i = 0; i < 4; i++) {                                     \
            int idx = tid + i * 256;                                      \
            int r = idx >> 3, c = idx & 7;                                \
            ra[i] = Xv[(size_t)(m0 + r) * (D_ / 4) + kb + c];             \
            rb[i] = Wv4[(size_t)(n0 + r) * (D_ / 4) + kb + c];            \
        }                                                                 \
    }

#define STS_STAGE(bf)                                                     \
    {                                                                     \
        for (int i = 0; i < 4; i++) {                                     \
            int idx = tid + i * 256;                                      \
            int r = idx >> 3, c = idx & 7;                                \
            *(uint2*)&As[bf][r][c * 4] = f4_to_h4(ra[i]);                 \
            *(uint2*)&Bs[bf][r][c * 4] = f4_to_h4(rb[i]);                 \
        }                                                                 \
    }

    LDG_STAGE(0);
    STS_STAGE(0);
    __syncthreads();

    const uint32_t sA = smem_u32(&As[0][0][0]);
    const uint32_t sB = smem_u32(&Bs[0][0][0]);
    const uint32_t bufBytesA = BM * KSTRIDE * 2;
    const uint32_t bufBytesB = BN * KSTRIDE * 2;

    int buf = 0;
    for (int kt = 0; kt < KTILES; ++kt) {
        if (kt + 1 < KTILES) LDG_STAGE(kt + 1);

        uint32_t sAb = sA + buf * bufBytesA;
        uint32_t sBb = sB + buf * bufBytesB;
#pragma unroll
        for (int kk = 0; kk < BK; kk += 16) {
            uint32_t af[4][4];
            uint32_t bfg[4][2];
#pragma unroll
            for (int mi = 0; mi < 4; mi++) {
                int ar = wm * 64 + mi * 16 + (lane & 15);
                int ac = kk + ((lane >> 4) << 3);
                ldsm_x4(af[mi], sAb + (uint32_t)(ar * KSTRIDE + ac) * 2);
            }
#pragma unroll
            for (int ni = 0; ni < 4; ni++) {
                int l = lane & 15;
                int br = wn * 32 + ni * 8 + (l & 7);
                int bc = kk + ((l >> 3) << 3);
                ldsm_x2(bfg[ni], sBb + (uint32_t)(br * KSTRIDE + bc) * 2);
            }
#pragma unroll
            for (int mi = 0; mi < 4; mi++)
#pragma unroll
                for (int ni = 0; ni < 4; ni++)
                    mma16816(acc[mi][ni], af[mi], bfg[ni]);
        }

        if (kt + 1 < KTILES) STS_STAGE(buf ^ 1);
        __syncthreads();
        buf ^= 1;
    }

    // epilogue: y = c + bias; accumulate y^2 per row; atomicAdd to normOut
#pragma unroll
    for (int mi = 0; mi < 4; mi++) {
        float rs0 = 0.f, rs1 = 0.f;
#pragma unroll
        for (int ni = 0; ni < 4; ni++) {
            int nl = wn * 32 + ni * 8 + 2 * (lane & 3);
            float b0 = sb[nl], b1 = sb[nl + 1];
            float y0 = acc[mi][ni][0] + b0;
            float y1 = acc[mi][ni][1] + b1;
            float y2 = acc[mi][ni][2] + b0;
            float y3 = acc[mi][ni][3] + b1;
            rs0 += y0 * y0 + y1 * y1;
            rs1 += y2 * y2 + y3 * y3;
        }
        rs0 += __shfl_xor_sync(~0u, rs0, 1);
        rs0 += __shfl_xor_sync(~0u, rs0, 2);
        rs1 += __shfl_xor_sync(~0u, rs1, 1);
        rs1 += __shfl_xor_sync(~0u, rs1, 2);
        if ((lane & 3) == 0) {
            int row = m0 + wm * 64 + mi * 16 + (lane >> 2);
            atomicAdd(&normOut[row], rs0);
            atomicAdd(&normOut[row + 8], rs1);
        }
    }
#undef LDG_STAGE
#undef STS_STAGE
}

// ---------------- batch co-occurrence counts --------------------------------
__global__ void bcc_kernel(const int* __restrict__ labels) {
    __shared__ unsigned s_mask[256];
    int b = blockIdx.x * 256 + threadIdx.x;
    unsigned m = 0;
#pragma unroll
    for (int k = 0; k < K_; k++) m |= (labels[(size_t)b * K_ + k] != 0 ? 1u : 0u) << k;
    s_mask[threadIdx.x] = m;
    __syncthreads();
    if (threadIdx.x < K_ * K_) {
        int i = threadIdx.x / K_, j = threadIdx.x % K_;
        int cnt = 0;
        for (int r = 0; r < 256; ++r) {
            unsigned mm = s_mask[r];
            cnt += (int)(((mm >> i) & 1u) & ((mm >> j) & 1u));
        }
        atomicAdd(&g_bcc[threadIdx.x], cnt);
    }
}

// ---------------- shapley: numerators (fp32) / norms, write output ----------
__global__ void shapley_kernel(const float* __restrict__ img,
                               const float* __restrict__ txt,
                               const int* __restrict__ labels,
                               float* __restrict__ out) {
    int b = blockIdx.x, tid = threadIdx.x;  // 128 threads
    float av[QP], at_[QP];
#pragma unroll
    for (int k = 0; k < QP; k++) { av[k] = 0.f; at_[k] = 0.f; }
    const float4* qv4 = (const float4*)g_qv;
    const float4* qt4 = (const float4*)g_qt;
    for (int i = tid; i < D_; i += 128) {
        float xi = img[(size_t)b * D_ + i];
        float ti = txt[(size_t)b * D_ + i];
#pragma unroll
        for (int c = 0; c < 4; c++) {
            float4 v = qv4[i * 4 + c];
            float4 w = qt4[i * 4 + c];
            av[c * 4 + 0] += xi * v.x; av[c * 4 + 1] += xi * v.y;
            av[c * 4 + 2] += xi * v.z; av[c * 4 + 3] += xi * v.w;
            at_[c * 4 + 0] += ti * w.x; at_[c * 4 + 1] += ti * w.y;
            at_[c * 4 + 2] += ti * w.z; at_[c * 4 + 3] += ti * w.w;
        }
    }
#pragma unroll
    for (int k = 0; k < K_; k++) {
        for (int off = 16; off; off >>= 1) {
            av[k]  += __shfl_xor_sync(~0u, av[k], off);
            at_[k] += __shfl_xor_sync(~0u, at_[k], off);
        }
    }
    __shared__ float sv[4][K_], st[4][K_];
    int warp = tid >> 5, lane = tid & 31;
    if (lane == 0) {
#pragma unroll
        for (int k = 0; k < K_; k++) { sv[warp][k] = av[k]; st[warp][k] = at_[k]; }
    }
    __syncthreads();
    if (tid < K_) {
        float nv = sqrtf(g_normv[b]);
        float nt = sqrtf(g_normt[b]);
        float numv = sv[0][tid] + sv[1][tid] + sv[2][tid] + sv[3][tid] + g_cv[tid];
        float numt = st[0][tid] + st[1][tid] + st[2][tid] + st[3][tid] + g_ct[tid];
        float vs = numv / fmaxf(nv, 1e-12f);
        float ts = numt / fmaxf(nt, 1e-12f);
        out[(size_t)b * K_ + tid] =
            0.5f * (vs + ts) * (float)labels[(size_t)b * K_ + tid];
    }
}

// ---------------- cooccur loss + prototype passthrough ----------------------
__global__ void loss_kernel(const float* __restrict__ coocc, float* __restrict__ out_loss) {
    int t = threadIdx.x;
    float d = 0.f;
    if (t < K_ * K_) {
        float bc = (float)g_bcc[t] / (float)B_;
        float sg = 1.0f / (1.0f + expf(-coocc[t]));
        float e = sg - bc;
        d = e * e;
    }
    for (int off = 16; off; off >>= 1) d += __shfl_xor_sync(~0u, d, off);
    __shared__ float r[8];
    int warp = t >> 5, lane = t & 31;
    if (lane == 0) r[warp] = d;
    __syncthreads();
    if (t == 0) {
        float S = 0.f;
        for (int w = 0; w < 8; w++) S += r[w];
        out_loss[0] = S / (float)(K_ * K_);
    }
}

__global__ void copy_proto_kernel(const float* __restrict__ proto, float* __restrict__ dst) {
    int idx = blockIdx.x * blockDim.x + threadIdx.x;
    if (idx < K_ * D_) dst[idx] = proto[idx];
}

// ---------------- launch ----------------------------------------------------
extern "C" void kernel_launch(void* const* d_in, const int* in_sizes, int n_in,
                              void* d_out, int out_size) {
    const float* img    = (const float*)d_in[0];
    const float* txt    = (const float*)d_in[1];
    const int*   labels = (const int*)d_in[2];
    const float* Wv     = (const float*)d_in[3];
    const float* bv     = (const float*)d_in[4];
    const float* Wt     = (const float*)d_in[5];
    const float* bt     = (const float*)d_in[6];
    const float* proto  = (const float*)d_in[7];
    const float* coocc  = (const float*)d_in[8];
    float* out = (float*)d_out;

    zero_kernel<<<256, 256>>>();
    phat_kernel<<<K_, 256>>>(proto, bv, bt);
    q_kernel<<<dim3(16, 8, 2), 256>>>(Wv, Wt);

    dim3 ggrid(D_ / BN, B_ / BM);
    norm_gemm<<<ggrid, 256>>>(img, Wv, bv, 0);
    norm_gemm<<<ggrid, 256>>>(txt, Wt, bt, 1);

    bcc_kernel<<<B_ / 256, 256>>>(labels);
    shapley_kernel<<<B_, 128>>>(img, txt, labels, out);

    if (out_size >= B_ * K_ + K_ * D_ + 1) {
        copy_proto_kernel<<<(K_ * D_ + 255) / 256, 256>>>(proto, out + (size_t)B_ * K_);
        loss_kernel<<<1, 256>>>(coocc, out + (size_t)B_ * K_ + (size_t)K_ * D_);
    }
}